// round 4
// baseline (speedup 1.0000x reference)
#include <cuda_runtime.h>

// ---------------------------------------------------------------------------
// Constants: B=16, T=32, NP=8, NG=4, J=14, H=256
// ---------------------------------------------------------------------------
#define BT         512
#define NP         8
#define NG         4
#define JD         42            // J*3
#define NPERM      1680
#define HM_ELEMS   33554432
#define HM_F4      (HM_ELEMS / 4)      // 8388608 float4
#define NBLOCKS    512
#define HEAT_THREADS 256
#define NTHREADS   288                  // 8 heat warps + 1 match warp
#define TILE_F4    2048                 // 32KB per tile
#define TILES_PER_BLOCK 8               // 512*8*2048 = 8388608  (exact)
#define HEAT_WARPS 8

// scratch (device globals — no allocation)
__device__ float g_hm_part[NBLOCKS * HEAT_WARPS];   // per-warp partials
__device__ float g_mp_off[BT];
__device__ float g_mp_sz[BT];
__device__ float g_mp_pose[BT];
__device__ unsigned int g_count = 0;   // self-resetting arrival counter

// ---------------------------------------------------------------------------
__device__ __forceinline__ unsigned int fkey(float f) {
    unsigned int u = __float_as_uint(f);
    return (u & 0x80000000u) ? ~u : (u | 0x80000000u);   // order-preserving
}

__device__ __forceinline__ void decode_perm(int p, int r[4]) {
    int avail[8] = {0, 1, 2, 3, 4, 5, 6, 7};
    const int div[4] = {210, 30, 5, 1};
    int n = 8;
    #pragma unroll
    for (int k = 0; k < 4; k++) {
        int idx = p / div[k];
        p -= idx * div[k];
        r[k] = avail[idx];
        for (int m = idx; m < n - 1; m++) avail[m] = avail[m + 1];
        n--;
    }
}

__device__ __forceinline__ unsigned long long warp_min_u64(unsigned long long v) {
    #pragma unroll
    for (int off = 16; off > 0; off >>= 1) {
        unsigned long long o = __shfl_xor_sync(0xFFFFFFFFu, v, off);
        v = min(v, o);
    }
    return v;
}

__device__ __forceinline__ double warp_red_d(double v) {
    #pragma unroll
    for (int off = 16; off > 0; off >>= 1)
        v += __shfl_down_sync(0xFFFFFFFFu, v, off);
    return v;
}

// ---------------------------------------------------------------------------
// 512 persistent blocks x 288 threads.
//   threads [0,256)  : stream 8 contiguous 32KB tiles of heatmap MSE
//   threads [256,288): Hungarian match for bt = blockIdx.x (concurrent)
//   last arriving block: final reduce + write + reset counter
// ---------------------------------------------------------------------------
__global__ void __launch_bounds__(NTHREADS, 3)
fused_loss_kernel(const float4* __restrict__ hm_pred,
                  const float4* __restrict__ hm_gt,
                  const float* __restrict__ hor_offset,   // [BT,8,2]
                  const float* __restrict__ hor_bsize,    // [BT,8,4]
                  const float* __restrict__ hor_center,   // [BT,8,2]
                  const float* __restrict__ scores,       // [BT,8]
                  const float* __restrict__ x_pose3d,     // [BT,8,42]
                  const float* __restrict__ gt_wh,        // [BT,4,4]
                  const float* __restrict__ gt_off,       // [BT,4,2]
                  const float* __restrict__ gt_center,    // [BT,4,2]
                  const float* __restrict__ gt_pose,      // [BT,4,42]
                  float* __restrict__ out)
{
    const int bid = blockIdx.x;
    const int tid = threadIdx.x;

    __shared__ float pc[NP * 2], gc[NG * 2], sc[NP];
    __shared__ float po[NP * 2], go[NG * 2];
    __shared__ float ps[NP * 4], gs[NG * 4];
    __shared__ float pp[NP * JD], gp[NG * JD];
    __shared__ float Cb[NP][NG], Cp[NP][NG];

    if (tid < HEAT_THREADS) {
        // ================= heatmap MSE: 8 contiguous tiles =================
        const size_t base0 = (size_t)bid * TILES_PER_BLOCK * TILE_F4;
        const float4* pa = hm_pred + base0;
        const float4* pb = hm_gt   + base0;
        float s0 = 0.f, s1 = 0.f, s2 = 0.f, s3 = 0.f;
        #pragma unroll
        for (int t = 0; t < TILES_PER_BLOCK; t++) {
            const int tbase = t * TILE_F4;
            #pragma unroll
            for (int g = 0; g < 2; g++) {
                float4 av[4], bv[4];
                #pragma unroll
                for (int u = 0; u < 4; u++) {
                    int idx = tbase + (g * 4 + u) * HEAT_THREADS + tid;
                    av[u] = __ldg(&pa[idx]);
                    bv[u] = __ldg(&pb[idx]);
                }
                #pragma unroll
                for (int u = 0; u < 4; u++) {
                    float dx = av[u].x - bv[u].x, dy = av[u].y - bv[u].y;
                    float dz = av[u].z - bv[u].z, dw = av[u].w - bv[u].w;
                    s0 += dx * dx; s1 += dy * dy; s2 += dz * dz; s3 += dw * dw;
                }
            }
        }
        float s = (s0 + s1) + (s2 + s3);
        #pragma unroll
        for (int off = 16; off > 0; off >>= 1)
            s += __shfl_down_sync(0xFFFFFFFFu, s, off);
        if ((tid & 31) == 0)
            g_hm_part[bid * HEAT_WARPS + (tid >> 5)] = s;
    } else {
        // ================= Hungarian match, 1 warp, bt = bid ================
        const int lane = tid - HEAT_THREADS;     // 0..31
        const int bt = bid;

        for (int k = lane; k < NP * 2; k += 32) pc[k] = hor_center[bt * NP * 2 + k];
        for (int k = lane; k < NG * 2; k += 32) gc[k] = gt_center[bt * NG * 2 + k];
        for (int k = lane; k < NP;     k += 32) sc[k] = scores[bt * NP + k];
        for (int k = lane; k < NP * 2; k += 32) po[k] = hor_offset[bt * NP * 2 + k];
        for (int k = lane; k < NG * 2; k += 32) go[k] = gt_off[bt * NG * 2 + k];
        for (int k = lane; k < NP * 4; k += 32) ps[k] = hor_bsize[bt * NP * 4 + k];
        for (int k = lane; k < NG * 4; k += 32) gs[k] = gt_wh[bt * NG * 4 + k];
        for (int k = lane; k < NP * JD; k += 32) pp[k] = x_pose3d[bt * NP * JD + k];
        for (int k = lane; k < NG * JD; k += 32) gp[k] = gt_pose[bt * NG * JD + k];
        __syncwarp();

        // cost matrices: each lane handles one (i,j)
        {
            int i = lane >> 2, j = lane & 3;
            float dx = pc[i * 2 + 0] - gc[j * 2 + 0];
            float dy = pc[i * 2 + 1] - gc[j * 2 + 1];
            Cb[i][j] = sqrtf(dx * dx + dy * dy) - sc[i];
            float acc = 0.0f;
            #pragma unroll
            for (int k = 0; k < JD; k++) {
                float d = pp[i * JD + k] - gp[j * JD + k];
                acc += d * d;
            }
            Cp[i][j] = sqrtf(acc);
        }
        __syncwarp();

        unsigned long long lb = ~0ULL, lp = ~0ULL;
        for (int p = lane; p < NPERM; p += 32) {
            int r[4];
            decode_perm(p, r);
            float cb = Cb[r[0]][0] + Cb[r[1]][1] + Cb[r[2]][2] + Cb[r[3]][3];
            float cp = Cp[r[0]][0] + Cp[r[1]][1] + Cp[r[2]][2] + Cp[r[3]][3];
            lb = min(lb, ((unsigned long long)fkey(cb) << 32) | (unsigned)p);
            lp = min(lp, ((unsigned long long)fkey(cp) << 32) | (unsigned)p);
        }
        lb = warp_min_u64(lb);
        lp = warp_min_u64(lp);

        if (lane == 0) {
            int r[4];
            decode_perm((int)(lb & 0xFFFFFFFFu), r);
            float off = 0.0f, sz = 0.0f;
            #pragma unroll
            for (int j = 0; j < NG; j++) {
                int i = r[j];
                off += 0.5f * (fabsf(po[i * 2 + 0] - go[j * 2 + 0]) +
                               fabsf(po[i * 2 + 1] - go[j * 2 + 1]));
                float s4 = 0.0f;
                #pragma unroll
                for (int k = 0; k < 4; k++) s4 += fabsf(ps[i * 4 + k] - gs[j * 4 + k]);
                sz += 0.25f * s4;
            }
            g_mp_off[bt] = off;
            g_mp_sz[bt]  = sz;
        }
        if (lane == 1) {
            int r[4];
            decode_perm((int)(lp & 0xFFFFFFFFu), r);
            float s = 0.0f;
            #pragma unroll
            for (int j = 0; j < NG; j++) {
                int i = r[j];
                for (int k = 0; k < JD; k++) {
                    float d = pp[i * JD + k] - gp[j * JD + k];
                    s += d * d;
                }
            }
            g_mp_pose[bt] = s;
        }
    }

    // ---------------- arrival + last-block finalize ----------------
    __syncthreads();
    __shared__ bool isLast;
    if (tid == 0) {
        __threadfence();
        isLast = (atomicAdd(&g_count, 1u) == NBLOCKS - 1);
    }
    __syncthreads();
    if (!isLast) return;

    double a0 = 0.0, a1 = 0.0, a2 = 0.0, a3 = 0.0;
    for (int k = tid; k < NBLOCKS * HEAT_WARPS; k += NTHREADS) a0 += (double)g_hm_part[k];
    for (int k = tid; k < BT; k += NTHREADS) {
        a1 += (double)g_mp_off[k];
        a2 += (double)g_mp_sz[k];
        a3 += (double)g_mp_pose[k];
    }
    a0 = warp_red_d(a0); a1 = warp_red_d(a1); a2 = warp_red_d(a2); a3 = warp_red_d(a3);
    __shared__ double wd[9][4];
    int lane = tid & 31, wid = tid >> 5;   // 9 warps
    if (lane == 0) { wd[wid][0] = a0; wd[wid][1] = a1; wd[wid][2] = a2; wd[wid][3] = a3; }
    __syncthreads();
    if (wid == 0) {
        double v0 = (lane < 9) ? wd[lane][0] : 0.0;
        double v1 = (lane < 9) ? wd[lane][1] : 0.0;
        double v2 = (lane < 9) ? wd[lane][2] : 0.0;
        double v3 = (lane < 9) ? wd[lane][3] : 0.0;
        #pragma unroll
        for (int off = 8; off > 0; off >>= 1) {
            v0 += __shfl_down_sync(0xFFFFFFFFu, v0, off);
            v1 += __shfl_down_sync(0xFFFFFFFFu, v1, off);
            v2 += __shfl_down_sync(0xFFFFFFFFu, v2, off);
            v3 += __shfl_down_sync(0xFFFFFFFFu, v3, off);
        }
        if (lane == 0) {
            double center = v0 / (double)HM_ELEMS;
            double offL   = v1 / (double)BT;
            double szL    = v2 / (double)BT;
            double poseL  = v3 / (double)(BT * NP * 14);
            out[0] = (float)(center + offL + szL + poseL);
            g_count = 0;   // reset for next graph replay
        }
    }
}

extern "C" void kernel_launch(void* const* d_in, const int* in_sizes, int n_in,
                              void* d_out, int out_size) {
    const float* hor_heatmap = (const float*)d_in[0];
    const float* hor_offset  = (const float*)d_in[1];
    const float* hor_bsize   = (const float*)d_in[2];
    const float* hor_center  = (const float*)d_in[3];
    const float* scores      = (const float*)d_in[4];
    const float* x_pose3d    = (const float*)d_in[5];
    const float* gt_heatmap  = (const float*)d_in[6];
    const float* gt_wh       = (const float*)d_in[7];
    const float* gt_off      = (const float*)d_in[8];
    const float* gt_center   = (const float*)d_in[9];
    const float* gt_pose     = (const float*)d_in[10];
    float* out = (float*)d_out;

    fused_loss_kernel<<<NBLOCKS, NTHREADS>>>(
        (const float4*)hor_heatmap, (const float4*)gt_heatmap,
        hor_offset, hor_bsize, hor_center, scores, x_pose3d,
        gt_wh, gt_off, gt_center, gt_pose, out);
}

// round 7
// speedup vs baseline: 2.1505x; 2.1505x over previous
#include <cuda_runtime.h>

// ---------------------------------------------------------------------------
// Constants: B=16, T=32, NP=8, NG=4, J=14, H=256
// ---------------------------------------------------------------------------
#define BT         512
#define NP         8
#define NG         4
#define JD         42            // J*3
#define NPERM      1680
#define HM_ELEMS   33554432
#define HM_F4      (HM_ELEMS / 4)     // 8388608 float4
#define HM_BLOCKS  8192
#define CHUNK_F4   1024               // 16KB chunk per block
#define NTHREADS   256
#define TOTAL_BLOCKS (BT + HM_BLOCKS) // match blocks first

// scratch (device globals — no allocation)
__device__ float g_hm_part[HM_BLOCKS];
__device__ float g_mp_off[BT];
__device__ float g_mp_sz[BT];
__device__ float g_mp_pose[BT];
__device__ unsigned int g_count = 0;   // self-resetting arrival counter

// ---------------------------------------------------------------------------
__device__ __forceinline__ unsigned int fkey(float f) {
    unsigned int u = __float_as_uint(f);
    return (u & 0x80000000u) ? ~u : (u | 0x80000000u);   // order-preserving
}

__device__ __forceinline__ void decode_perm(int p, int r[4]) {
    int avail[8] = {0, 1, 2, 3, 4, 5, 6, 7};
    const int div[4] = {210, 30, 5, 1};
    int n = 8;
    #pragma unroll
    for (int k = 0; k < 4; k++) {
        int idx = p / div[k];
        p -= idx * div[k];
        r[k] = avail[idx];
        for (int m = idx; m < n - 1; m++) avail[m] = avail[m + 1];
        n--;
    }
}

__device__ __forceinline__ double warp_red_d(double v) {
    #pragma unroll
    for (int off = 16; off > 0; off >>= 1)
        v += __shfl_down_sync(0xFFFFFFFFu, v, off);
    return v;
}

// ---------------------------------------------------------------------------
//   blocks [0, BT)       : Hungarian match for bt = bid  (wave 1, hidden)
//   blocks [BT, TOTAL)   : heatmap MSE, contiguous 16KB chunk, batched loads
//   last arriving block  : final reduce + write + reset counter
// ---------------------------------------------------------------------------
__global__ void __launch_bounds__(NTHREADS)
fused_loss_kernel(const float4* __restrict__ hm_pred,
                  const float4* __restrict__ hm_gt,
                  const float* __restrict__ hor_offset,   // [BT,8,2]
                  const float* __restrict__ hor_bsize,    // [BT,8,4]
                  const float* __restrict__ hor_center,   // [BT,8,2]
                  const float* __restrict__ scores,       // [BT,8]
                  const float* __restrict__ x_pose3d,     // [BT,8,42]
                  const float* __restrict__ gt_wh,        // [BT,4,4]
                  const float* __restrict__ gt_off,       // [BT,4,2]
                  const float* __restrict__ gt_center,    // [BT,4,2]
                  const float* __restrict__ gt_pose,      // [BT,4,42]
                  float* __restrict__ out)
{
    const int bid = blockIdx.x;
    const int tid = threadIdx.x;

    if (bid >= BT) {
        // ============ heatmap MSE: 16KB chunk, 2 groups of 4 batched loads
        const int hm_bid = bid - BT;
        const float4* pa = hm_pred + (size_t)hm_bid * CHUNK_F4;
        const float4* pb = hm_gt   + (size_t)hm_bid * CHUNK_F4;

        // group 1: indices tid, tid+256
        float4 a0 = __ldcs(&pa[tid]);
        float4 a1 = __ldcs(&pa[tid + NTHREADS]);
        float4 b0 = __ldcs(&pb[tid]);
        float4 b1 = __ldcs(&pb[tid + NTHREADS]);
        // group 2: indices tid+512, tid+768 (ptxas may hoist above group-1 FMAs)
        float4 a2 = __ldcs(&pa[tid + 2 * NTHREADS]);
        float4 a3 = __ldcs(&pa[tid + 3 * NTHREADS]);
        float4 b2 = __ldcs(&pb[tid + 2 * NTHREADS]);
        float4 b3 = __ldcs(&pb[tid + 3 * NTHREADS]);

        float s0, s1, s2, s3;
        {
            float dx = a0.x - b0.x, dy = a0.y - b0.y, dz = a0.z - b0.z, dw = a0.w - b0.w;
            s0 = dx * dx; s1 = dy * dy; s2 = dz * dz; s3 = dw * dw;
        }
        {
            float dx = a1.x - b1.x, dy = a1.y - b1.y, dz = a1.z - b1.z, dw = a1.w - b1.w;
            s0 += dx * dx; s1 += dy * dy; s2 += dz * dz; s3 += dw * dw;
        }
        {
            float dx = a2.x - b2.x, dy = a2.y - b2.y, dz = a2.z - b2.z, dw = a2.w - b2.w;
            s0 += dx * dx; s1 += dy * dy; s2 += dz * dz; s3 += dw * dw;
        }
        {
            float dx = a3.x - b3.x, dy = a3.y - b3.y, dz = a3.z - b3.z, dw = a3.w - b3.w;
            s0 += dx * dx; s1 += dy * dy; s2 += dz * dz; s3 += dw * dw;
        }
        float s = (s0 + s1) + (s2 + s3);
        #pragma unroll
        for (int off = 16; off > 0; off >>= 1)
            s += __shfl_down_sync(0xFFFFFFFFu, s, off);
        __shared__ float ws[8];
        int lane = tid & 31, wid = tid >> 5;
        if (lane == 0) ws[wid] = s;
        __syncthreads();
        if (wid == 0) {
            float v = (lane < 8) ? ws[lane] : 0.0f;
            #pragma unroll
            for (int off = 4; off > 0; off >>= 1)
                v += __shfl_down_sync(0xFFFFFFFFu, v, off);
            if (lane == 0) g_hm_part[hm_bid] = v;
        }
    } else {
        // ============ Hungarian match for one (b,t) ============
        const int bt = bid;

        __shared__ float pc[NP * 2], gc[NG * 2], sc[NP];
        __shared__ float po[NP * 2], go[NG * 2];
        __shared__ float ps[NP * 4], gs[NG * 4];
        __shared__ float pp[NP * JD], gp[NG * JD];
        __shared__ float Cb[NP][NG], Cp[NP][NG];
        __shared__ unsigned long long bestBox, bestPose;

        for (int k = tid; k < NP * 2; k += NTHREADS) pc[k] = hor_center[bt * NP * 2 + k];
        for (int k = tid; k < NG * 2; k += NTHREADS) gc[k] = gt_center[bt * NG * 2 + k];
        for (int k = tid; k < NP;     k += NTHREADS) sc[k] = scores[bt * NP + k];
        for (int k = tid; k < NP * 2; k += NTHREADS) po[k] = hor_offset[bt * NP * 2 + k];
        for (int k = tid; k < NG * 2; k += NTHREADS) go[k] = gt_off[bt * NG * 2 + k];
        for (int k = tid; k < NP * 4; k += NTHREADS) ps[k] = hor_bsize[bt * NP * 4 + k];
        for (int k = tid; k < NG * 4; k += NTHREADS) gs[k] = gt_wh[bt * NG * 4 + k];
        for (int k = tid; k < NP * JD; k += NTHREADS) pp[k] = x_pose3d[bt * NP * JD + k];
        for (int k = tid; k < NG * JD; k += NTHREADS) gp[k] = gt_pose[bt * NG * JD + k];
        if (tid == 0) { bestBox = ~0ULL; bestPose = ~0ULL; }
        __syncthreads();

        if (tid < NP * NG) {
            int i = tid >> 2, j = tid & 3;
            float dx = pc[i * 2 + 0] - gc[j * 2 + 0];
            float dy = pc[i * 2 + 1] - gc[j * 2 + 1];
            Cb[i][j] = sqrtf(dx * dx + dy * dy) - sc[i];
            float acc = 0.0f;
            for (int k = 0; k < JD; k++) {
                float d = pp[i * JD + k] - gp[j * JD + k];
                acc += d * d;
            }
            Cp[i][j] = sqrtf(acc);
        }
        __syncthreads();

        unsigned long long lb = ~0ULL, lp = ~0ULL;
        for (int p = tid; p < NPERM; p += NTHREADS) {
            int r[4];
            decode_perm(p, r);
            float cb = Cb[r[0]][0] + Cb[r[1]][1] + Cb[r[2]][2] + Cb[r[3]][3];
            float cp = Cp[r[0]][0] + Cp[r[1]][1] + Cp[r[2]][2] + Cp[r[3]][3];
            lb = min(lb, ((unsigned long long)fkey(cb) << 32) | (unsigned)p);
            lp = min(lp, ((unsigned long long)fkey(cp) << 32) | (unsigned)p);
        }
        atomicMin(&bestBox, lb);
        atomicMin(&bestPose, lp);
        __syncthreads();

        if (tid == 0) {
            int r[4];
            decode_perm((int)(bestBox & 0xFFFFFFFFu), r);
            float off = 0.0f, sz = 0.0f;
            #pragma unroll
            for (int j = 0; j < NG; j++) {
                int i = r[j];
                off += 0.5f * (fabsf(po[i * 2 + 0] - go[j * 2 + 0]) +
                               fabsf(po[i * 2 + 1] - go[j * 2 + 1]));
                float s4 = 0.0f;
                #pragma unroll
                for (int k = 0; k < 4; k++) s4 += fabsf(ps[i * 4 + k] - gs[j * 4 + k]);
                sz += 0.25f * s4;
            }
            g_mp_off[bt] = off;
            g_mp_sz[bt]  = sz;
        }
        if (tid == 1) {
            int r[4];
            decode_perm((int)(bestPose & 0xFFFFFFFFu), r);
            float s = 0.0f;
            #pragma unroll
            for (int j = 0; j < NG; j++) {
                int i = r[j];
                for (int k = 0; k < JD; k++) {
                    float d = pp[i * JD + k] - gp[j * JD + k];
                    s += d * d;
                }
            }
            g_mp_pose[bt] = s;
        }
    }

    // ---------------- arrival + last-block finalize ----------------
    __syncthreads();
    __shared__ bool isLast;
    if (tid == 0) {
        __threadfence();
        isLast = (atomicAdd(&g_count, 1u) == TOTAL_BLOCKS - 1);
    }
    __syncthreads();
    if (!isLast) return;

    double a0 = 0.0, a1 = 0.0, a2 = 0.0, a3 = 0.0;
    for (int k = tid; k < HM_BLOCKS; k += NTHREADS) a0 += (double)g_hm_part[k];
    for (int k = tid; k < BT; k += NTHREADS) {
        a1 += (double)g_mp_off[k];
        a2 += (double)g_mp_sz[k];
        a3 += (double)g_mp_pose[k];
    }
    a0 = warp_red_d(a0); a1 = warp_red_d(a1); a2 = warp_red_d(a2); a3 = warp_red_d(a3);
    __shared__ double wd[8][4];
    int lane = tid & 31, wid = tid >> 5;
    if (lane == 0) { wd[wid][0] = a0; wd[wid][1] = a1; wd[wid][2] = a2; wd[wid][3] = a3; }
    __syncthreads();
    if (wid == 0) {
        double v0 = (lane < 8) ? wd[lane][0] : 0.0;
        double v1 = (lane < 8) ? wd[lane][1] : 0.0;
        double v2 = (lane < 8) ? wd[lane][2] : 0.0;
        double v3 = (lane < 8) ? wd[lane][3] : 0.0;
        #pragma unroll
        for (int off = 4; off > 0; off >>= 1) {
            v0 += __shfl_down_sync(0xFFFFFFFFu, v0, off);
            v1 += __shfl_down_sync(0xFFFFFFFFu, v1, off);
            v2 += __shfl_down_sync(0xFFFFFFFFu, v2, off);
            v3 += __shfl_down_sync(0xFFFFFFFFu, v3, off);
        }
        if (lane == 0) {
            double center = v0 / (double)HM_ELEMS;
            double offL   = v1 / (double)BT;
            double szL    = v2 / (double)BT;
            double poseL  = v3 / (double)(BT * NP * 14);
            out[0] = (float)(center + offL + szL + poseL);
            g_count = 0;   // reset for next graph replay
        }
    }
}

extern "C" void kernel_launch(void* const* d_in, const int* in_sizes, int n_in,
                              void* d_out, int out_size) {
    const float* hor_heatmap = (const float*)d_in[0];
    const float* hor_offset  = (const float*)d_in[1];
    const float* hor_bsize   = (const float*)d_in[2];
    const float* hor_center  = (const float*)d_in[3];
    const float* scores      = (const float*)d_in[4];
    const float* x_pose3d    = (const float*)d_in[5];
    const float* gt_heatmap  = (const float*)d_in[6];
    const float* gt_wh       = (const float*)d_in[7];
    const float* gt_off      = (const float*)d_in[8];
    const float* gt_center   = (const float*)d_in[9];
    const float* gt_pose     = (const float*)d_in[10];
    float* out = (float*)d_out;

    fused_loss_kernel<<<TOTAL_BLOCKS, NTHREADS>>>(
        (const float4*)hor_heatmap, (const float4*)gt_heatmap,
        hor_offset, hor_bsize, hor_center, scores, x_pose3d,
        gt_wh, gt_off, gt_center, gt_pose, out);
}